// round 8
// baseline (speedup 1.0000x reference)
#include <cuda_runtime.h>
#include <cuda_fp16.h>
#include <cstdint>

#define Bb 4
#define Ss 2048
#define Dd 1024

#define BM 128
#define BN 128
#define BK 64                                  // fp16: 64 * 2B = 128B per row
#define A_BYTES (BM * 128)                     // 16KB
#define STAGE_BYTES (2 * A_BYTES)              // 32KB
#define SMEM_BYTES (3 * STAGE_BYTES)           // 96KB, 3 stages

// ---------------- device scratch (allocation-free rule) ----------------
__device__ __align__(1024) __half g_x16[Bb * Ss * Dd];
__device__ __align__(1024) __half g_W16[3 * Dd * Dd];
__device__ __align__(1024) __half g_Q16[Bb * Ss * Dd];
__device__ __align__(1024) __half g_K16[Bb * Ss * Dd];
__device__ __align__(1024) __half g_Vt16[Bb * Ss * Dd];
__device__ __align__(1024) float  g_P32[Bb * Ss * Ss];
__device__ __align__(1024) __half g_P16[Bb * Ss * Ss];

// ---------------- helpers ----------------
__device__ __forceinline__ uint32_t smem_u32(const void* p) {
    uint32_t a;
    asm("{ .reg .u64 t; cvta.to.shared.u64 t, %1; cvt.u32.u64 %0, t; }" : "=r"(a) : "l"(p));
    return a;
}
__device__ __forceinline__ void cp16(uint32_t dst, const void* src) {
    asm volatile("cp.async.cg.shared.global [%0], [%1], 16;" :: "r"(dst), "l"(src));
}
__device__ __forceinline__ void cp_commit() {
    asm volatile("cp.async.commit_group;" ::: "memory");
}
__device__ __forceinline__ void cp_wait1() {
    asm volatile("cp.async.wait_group 1;" ::: "memory");
}
__device__ __forceinline__ void ldsm4(uint32_t& r0, uint32_t& r1, uint32_t& r2, uint32_t& r3,
                                      uint32_t addr) {
    asm volatile("ldmatrix.sync.aligned.m8n8.x4.shared.b16 {%0,%1,%2,%3}, [%4];"
                 : "=r"(r0), "=r"(r1), "=r"(r2), "=r"(r3) : "r"(addr));
}
__device__ __forceinline__ void mma_f16(float* c, const uint32_t* a, uint32_t b0, uint32_t b1) {
    asm volatile(
        "mma.sync.aligned.m16n8k16.row.col.f32.f16.f16.f32 "
        "{%0,%1,%2,%3}, {%4,%5,%6,%7}, {%8,%9}, {%0,%1,%2,%3};"
        : "+f"(c[0]), "+f"(c[1]), "+f"(c[2]), "+f"(c[3])
        : "r"(a[0]), "r"(a[1]), "r"(a[2]), "r"(a[3]), "r"(b0), "r"(b1));
}

// ======= shared fp16 mma.sync GEMM body: C[M,N] = A @ B^T * alpha (+bias) =======
// Address algebra: the XOR swizzle lives in bits [4:6] and every base is
// 128-aligned, so  As + row*128 + ((chunk ^ (row&7))<<4)
//   == (sb + row*128 + (((row&7)<<4) ^ (fkc<<4))) + cbuf*STAGE  ^  (ks<<5)
// The parenthesized term is a per-warp constant; per-ldsm cost = one LOP3-imm.
template <bool HALF_OUT>
__device__ __forceinline__ void gemm_body(
    const __half* __restrict__ Ab, const __half* __restrict__ Bg0,
    const float* __restrict__ bias, int biasMode,
    void* __restrict__ Cv, int Ntot, int Ktot, float alpha,
    int rowBase, int colBase, uint32_t sb)
{
    const int tid = threadIdx.x;
    const int lane = tid & 31;
    const int wid = tid >> 5;
    const int wm = wid & 1;        // 2 warps in M (64 rows each)
    const int wn = wid >> 1;       // 4 warps in N (32 cols each)

    // -------- loader precompute --------
    const int lr = tid >> 3;       // 0..31
    const int lc = tid & 7;        // 0..7
    uint32_t soff[4];
    int goff[4];
#pragma unroll
    for (int p = 0; p < 4; p++) {
        const int row = lr + 32 * p;
        soff[p] = row * 128 + ((uint32_t)(lc ^ (row & 7)) << 4);
        goff[p] = 32 * p * Ktot;
    }
    const __half* pA0 = Ab + (long long)lr * Ktot + lc * 8;
    const __half* pB0 = Bg0 + (long long)lr * Ktot + lc * 8;

    // -------- fragment address constants (swizzle + fkc folded in) --------
    const int frow = lane & 15;
    const uint32_t kf = (uint32_t)(lane >> 4) << 4;   // fkc<<4
    const uint32_t sxor = (((uint32_t)(frow & 7)) << 4) ^ kf;
    uint32_t QA[4], QB[2];
#pragma unroll
    for (int mt = 0; mt < 4; mt++) {
        const int r = wm * 64 + mt * 16 + frow;
        QA[mt] = sb + r * 128 + sxor;
    }
#pragma unroll
    for (int p = 0; p < 2; p++) {
        const int r = wn * 32 + p * 16 + frow;
        QB[p] = sb + A_BYTES + r * 128 + sxor;
    }

    float acc[4][4][4];
#pragma unroll
    for (int i = 0; i < 4; i++)
#pragma unroll
        for (int j = 0; j < 4; j++)
#pragma unroll
            for (int q = 0; q < 4; q++) acc[i][j][q] = 0.0f;

    const int kIters = Ktot / BK;

    auto load_stage = [&](int buf) {
        const uint32_t sbase = sb + buf * STAGE_BYTES;
#pragma unroll
        for (int p = 0; p < 4; p++) {
            cp16(sbase + soff[p], pA0 + goff[p]);
            cp16(sbase + A_BYTES + soff[p], pB0 + goff[p]);
        }
        pA0 += BK;
        pB0 += BK;
    };

    // prologue: stages 0 and 1 (kIters >= 2 always here)
    load_stage(0); cp_commit();
    load_stage(1); cp_commit();

    int nbuf = 2;   // next stage buffer to fill
    int cbuf = 0;   // stage buffer to consume
    for (int it = 0; it < kIters; it++) {
        cp_wait1();
        // Single barrier: all warps done reading buffer (it-1)%3 == nbuf before refill.
        __syncthreads();

        if (it + 2 < kIters) load_stage(nbuf);
        cp_commit();
        nbuf = (nbuf + 1 == 3) ? 0 : nbuf + 1;

        // per-iter fragment bases: 6 IADD
        const uint32_t so = (uint32_t)cbuf * STAGE_BYTES;
        cbuf = (cbuf + 1 == 3) ? 0 : cbuf + 1;
        uint32_t pa[4], pb[2];
#pragma unroll
        for (int mt = 0; mt < 4; mt++) pa[mt] = QA[mt] + so;
#pragma unroll
        for (int p = 0; p < 2; p++) pb[p] = QB[p] + so;

#pragma unroll
        for (int ks = 0; ks < 4; ks++) {            // 4 x k16 steps = K64
            const uint32_t kx = (uint32_t)ks << 5;  // immediate after unroll
            uint32_t a[4][4];
#pragma unroll
            for (int mt = 0; mt < 4; mt++)
                ldsm4(a[mt][0], a[mt][1], a[mt][2], a[mt][3], pa[mt] ^ kx);
            uint32_t b[2][4];
#pragma unroll
            for (int p = 0; p < 2; p++)
                ldsm4(b[p][0], b[p][1], b[p][2], b[p][3], pb[p] ^ kx);
#pragma unroll
            for (int mt = 0; mt < 4; mt++)
#pragma unroll
                for (int nt = 0; nt < 4; nt++) {
                    const int p = nt >> 1, o = nt & 1;
                    mma_f16(acc[mt][nt], a[mt], b[p][o], b[p][2 + o]);
                }
        }
    }

    // ---- epilogue ----
    const int g = lane >> 2;
    const int cpair = (lane & 3) * 2;
#pragma unroll
    for (int mt = 0; mt < 4; mt++) {
        const long long r0 = rowBase + wm * 64 + mt * 16 + g;
        const long long r1 = r0 + 8;
        float rb0 = 0.f, rb1 = 0.f;
        if (biasMode == 2) { rb0 = bias[r0]; rb1 = bias[r1]; }
#pragma unroll
        for (int nt = 0; nt < 4; nt++) {
            const int col = colBase + wn * 32 + nt * 8 + cpair;
            float bx = 0.f, by = 0.f;
            if (biasMode == 1) { bx = bias[col]; by = bias[col + 1]; }
            float2 v0, v1;
            v0.x = acc[mt][nt][0] * alpha + bx + rb0;
            v0.y = acc[mt][nt][1] * alpha + by + rb0;
            v1.x = acc[mt][nt][2] * alpha + bx + rb1;
            v1.y = acc[mt][nt][3] * alpha + by + rb1;
            if (HALF_OUT) {
                __half* Cb = (__half*)Cv;
                *reinterpret_cast<__half2*>(Cb + r0 * Ntot + col) = __floats2half2_rn(v0.x, v0.y);
                *reinterpret_cast<__half2*>(Cb + r1 * Ntot + col) = __floats2half2_rn(v1.x, v1.y);
            } else {
                float* Cb = (float*)Cv;
                *reinterpret_cast<float2*>(Cb + r0 * Ntot + col) = v0;
                *reinterpret_cast<float2*>(Cb + r1 * Ntot + col) = v1;
            }
        }
    }
}

// ======= merged QKV projection: 1536 linear CTAs =======
__global__ void __launch_bounds__(256, 2) proj_kernel(
    const __half* __restrict__ x16, const __half* __restrict__ W16,
    const float* __restrict__ bq, const float* __restrict__ bk, const float* __restrict__ bv,
    __half* __restrict__ Q16, __half* __restrict__ K16, __half* __restrict__ Vt16)
{
    extern __shared__ __align__(1024) char smem[];
    const uint32_t sb = smem_u32(smem);
    const long long SD = (long long)Ss * Dd;
    const long long DD = (long long)Dd * Dd;

    const int cta = blockIdx.x;
    if (cta < 1024) {
        const int z = cta >> 9;
        const int rem = cta & 511;
        const int y = rem >> 3, x = rem & 7;
        gemm_body<true>(x16 + (long long)y * BM * Dd,
                        W16 + z * DD + (long long)x * BN * Dd,
                        z ? bk : bq, 1,
                        z ? K16 : Q16, Dd, Dd, 1.0f, y * BM, x * BN, sb);
    } else {
        const int i = cta - 1024;
        const int bz = i >> 7;
        const int rem = i & 127;
        const int y = rem >> 4, x = rem & 15;
        gemm_body<true>(W16 + 2 * DD + (long long)y * BM * Dd,
                        x16 + bz * SD + (long long)x * BN * Dd,
                        bv, 2,
                        Vt16 + bz * SD, Ss, Dd, 1.0f, y * BM, x * BN, sb);
    }
}

// ======= batched GEMM (scores / PV), fp32 out, no bias =======
__global__ void __launch_bounds__(256, 2) bgemm_kernel(
    const __half* __restrict__ A, const __half* __restrict__ Bm,
    float* __restrict__ C, int Ntot, int Ktot, float alpha,
    long long sA, long long sB, long long sC)
{
    extern __shared__ __align__(1024) char smem[];
    const uint32_t sb = smem_u32(smem);
    const int bz = blockIdx.z;
    gemm_body<false>(A + bz * sA + (long long)blockIdx.y * BM * Ktot,
                     Bm + bz * sB + (long long)blockIdx.x * BN * Ktot,
                     nullptr, 0,
                     C + bz * sC, Ntot, Ktot, alpha,
                     blockIdx.y * BM, blockIdx.x * BN, sb);
}

// ---------------- merged fp32 -> fp16 convert (x and 3 weights) ----------------
__global__ void cvt_all_kernel(const float* __restrict__ x,
                               const float* __restrict__ wq, const float* __restrict__ wk,
                               const float* __restrict__ wv,
                               __half* __restrict__ x16, __half* __restrict__ W16)
{
    const int b = blockIdx.x;
    const int tid = threadIdx.x;
    const float* src;
    __half* dst;
    int i;
    if (b < 8192) {                 // x: 2097152 float4
        src = x; dst = x16; i = b * 256 + tid;
    } else {                        // weights: 262144 float4 each
        const int wb = b - 8192;
        const int w = wb >> 10;     // 0..2
        src = (w == 0) ? wq : (w == 1) ? wk : wv;
        dst = W16 + (long long)w * Dd * Dd;
        i = (wb & 1023) * 256 + tid;
    }
    const float4 v = reinterpret_cast<const float4*>(src)[i];
    __half2* o = reinterpret_cast<__half2*>(dst);
    o[2 * i]     = __floats2half2_rn(v.x, v.y);
    o[2 * i + 1] = __floats2half2_rn(v.z, v.w);
}

// ------- row softmax over S=2048: reads fp32 scores, writes fp16 P -------
__global__ void __launch_bounds__(256) softmax_kernel(const float* __restrict__ S32,
                                                      __half* __restrict__ P16)
{
    const float* row = S32 + (long long)blockIdx.x * Ss;
    __half* orow = P16 + (long long)blockIdx.x * Ss;
    const int tid = threadIdx.x;
    const int w = tid >> 5, l = tid & 31;

    float v[8];
    float m = -1e30f;
#pragma unroll
    for (int i = 0; i < 8; i++) { v[i] = row[tid + i * 256]; m = fmaxf(m, v[i]); }
#pragma unroll
    for (int o = 16; o > 0; o >>= 1) m = fmaxf(m, __shfl_xor_sync(0xFFFFFFFFu, m, o));

    __shared__ float smax[8], ssum[8];
    if (l == 0) smax[w] = m;
    __syncthreads();
    m = smax[0];
#pragma unroll
    for (int i = 1; i < 8; i++) m = fmaxf(m, smax[i]);

    float s = 0.0f;
#pragma unroll
    for (int i = 0; i < 8; i++) { v[i] = __expf(v[i] - m); s += v[i]; }
#pragma unroll
    for (int o = 16; o > 0; o >>= 1) s += __shfl_xor_sync(0xFFFFFFFFu, s, o);
    if (l == 0) ssum[w] = s;
    __syncthreads();
    float tot = 0.0f;
#pragma unroll
    for (int i = 0; i < 8; i++) tot += ssum[i];
    const float inv = 1.0f / tot;
#pragma unroll
    for (int i = 0; i < 8; i++) orow[tid + i * 256] = __float2half_rn(v[i] * inv);
}

// ---------------- host ----------------
extern "C" void kernel_launch(void* const* d_in, const int* in_sizes, int n_in,
                              void* d_out, int out_size)
{
    const float* x  = (const float*)d_in[0];
    const float* Wq = (const float*)d_in[1];
    const float* bq = (const float*)d_in[2];
    const float* Wk = (const float*)d_in[3];
    const float* bk = (const float*)d_in[4];
    const float* Wv = (const float*)d_in[5];
    const float* bv = (const float*)d_in[6];
    float* out = (float*)d_out;

    __half *x16, *W16, *Q16, *K16, *Vt16, *P16;
    float* P32;
    cudaGetSymbolAddress((void**)&x16, g_x16);
    cudaGetSymbolAddress((void**)&W16, g_W16);
    cudaGetSymbolAddress((void**)&Q16, g_Q16);
    cudaGetSymbolAddress((void**)&K16, g_K16);
    cudaGetSymbolAddress((void**)&Vt16, g_Vt16);
    cudaGetSymbolAddress((void**)&P32, g_P32);
    cudaGetSymbolAddress((void**)&P16, g_P16);

    cudaFuncSetAttribute((const void*)proj_kernel,
                         cudaFuncAttributeMaxDynamicSharedMemorySize, SMEM_BYTES);
    cudaFuncSetAttribute((const void*)bgemm_kernel,
                         cudaFuncAttributeMaxDynamicSharedMemorySize, SMEM_BYTES);

    // 0) one merged convert launch (x + 3 weights)
    cvt_all_kernel<<<8192 + 3072, 256>>>(x, Wq, Wk, Wv, x16, W16);

    const long long SD = (long long)Ss * Dd;
    const long long SS2 = (long long)Ss * Ss;

    // 1) merged Q/K/Vt projections: one 1536-CTA launch
    proj_kernel<<<1536, 256, SMEM_BYTES>>>(x16, W16, bq, bk, bv, Q16, K16, Vt16);

    // 2) scores = Q @ K^T / 32 -> fp32
    const dim3 g2(Ss / BN, Ss / BM, Bb);
    bgemm_kernel<<<g2, 256, SMEM_BYTES>>>(Q16, K16, P32, Ss, Dd, 0.03125f, SD, SD, SS2);

    // 3) softmax fp32 -> fp16 P
    softmax_kernel<<<Bb * Ss, 256>>>(P32, P16);

    // 4) out = P16 @ Vt16^T -> fp32
    const dim3 g3(Dd / BN, Ss / BM, Bb);
    bgemm_kernel<<<g3, 256, SMEM_BYTES>>>(P16, Vt16, out, Dd, Ss, 1.0f, SS2, SD, SD);
}

// round 9
// speedup vs baseline: 1.0107x; 1.0107x over previous
#include <cuda_runtime.h>
#include <cuda_fp16.h>
#include <cstdint>

#define Bb 4
#define Ss 2048
#define Dd 1024

#define BM 128
#define BN 128
#define BK 64                                  // fp16: 64 * 2B = 128B per row
#define A_BYTES (BM * 128)                     // 16KB
#define STAGE_BYTES (2 * A_BYTES)              // 32KB
#define SMEM_BYTES (3 * STAGE_BYTES)           // 96KB, 3 stages

// ---------------- device scratch (allocation-free rule) ----------------
__device__ __align__(1024) __half g_x16[Bb * Ss * Dd];
__device__ __align__(1024) __half g_W16[3 * Dd * Dd];
__device__ __align__(1024) __half g_Q16[Bb * Ss * Dd];
__device__ __align__(1024) __half g_K16[Bb * Ss * Dd];
__device__ __align__(1024) __half g_Vt16[Bb * Ss * Dd];
__device__ __align__(1024) float  g_P32[Bb * Ss * Ss];
__device__ __align__(1024) __half g_P16[Bb * Ss * Ss];

// ---------------- helpers ----------------
__device__ __forceinline__ uint32_t smem_u32(const void* p) {
    uint32_t a;
    asm("{ .reg .u64 t; cvta.to.shared.u64 t, %1; cvt.u32.u64 %0, t; }" : "=r"(a) : "l"(p));
    return a;
}
__device__ __forceinline__ void cp16(uint32_t dst, const void* src) {
    asm volatile("cp.async.cg.shared.global [%0], [%1], 16;" :: "r"(dst), "l"(src));
}
__device__ __forceinline__ void cp_commit() {
    asm volatile("cp.async.commit_group;" ::: "memory");
}
__device__ __forceinline__ void cp_wait1() {
    asm volatile("cp.async.wait_group 1;" ::: "memory");
}
__device__ __forceinline__ void ldsm4(uint32_t& r0, uint32_t& r1, uint32_t& r2, uint32_t& r3,
                                      uint32_t addr) {
    asm volatile("ldmatrix.sync.aligned.m8n8.x4.shared.b16 {%0,%1,%2,%3}, [%4];"
                 : "=r"(r0), "=r"(r1), "=r"(r2), "=r"(r3) : "r"(addr));
}
__device__ __forceinline__ void mma_f16(float* c, const uint32_t* a, uint32_t b0, uint32_t b1) {
    asm volatile(
        "mma.sync.aligned.m16n8k16.row.col.f32.f16.f16.f32 "
        "{%0,%1,%2,%3}, {%4,%5,%6,%7}, {%8,%9}, {%0,%1,%2,%3};"
        : "+f"(c[0]), "+f"(c[1]), "+f"(c[2]), "+f"(c[3])
        : "r"(a[0]), "r"(a[1]), "r"(a[2]), "r"(a[3]), "r"(b0), "r"(b1));
}

// ======= shared fp16 mma.sync GEMM body: C[M,N] = A @ B^T * alpha (+bias) =======
// Fragment addressing: QA/QB hold fully-resolved smem addresses for the CURRENT
// stage (swizzle + fkc folded in); per-ldsm cost is one LOP3 with the ks<<5
// immediate (chunk-XOR only toggles bits [4:6]); stage advance is an in-place
// increment (+32K,+32K,-64K), keeping register count identical to the arow/brow
// scheme (register parity with the 381us baseline is load-bearing: +6 live regs
// at the 128-reg/2-CTA cap caused the R8 spill regression).
template <bool HALF_OUT>
__device__ __forceinline__ void gemm_body(
    const __half* __restrict__ Ab, const __half* __restrict__ Bg0,
    const float* __restrict__ bias, int biasMode,
    void* __restrict__ Cv, int Ntot, int Ktot, float alpha,
    int rowBase, int colBase, uint32_t sb)
{
    const int tid = threadIdx.x;
    const int lane = tid & 31;
    const int wid = tid >> 5;
    const int wm = wid & 1;        // 2 warps in M (64 rows each)
    const int wn = wid >> 1;       // 4 warps in N (32 cols each)

    // -------- loader precompute (identical to 381us baseline) --------
    const int lr = tid >> 3;       // 0..31
    const int lc = tid & 7;        // 0..7
    uint32_t soff[4];
    const __half* pA[4];
    const __half* pB[4];
#pragma unroll
    for (int p = 0; p < 4; p++) {
        const int row = lr + 32 * p;
        soff[p] = row * 128 + ((uint32_t)(lc ^ (row & 7)) << 4);
        pA[p] = Ab + (long long)row * Ktot + lc * 8;
        pB[p] = Bg0 + (long long)row * Ktot + lc * 8;
    }

    // -------- fragment address constants (swizzle + fkc folded in) --------
    const int frow = lane & 15;
    const uint32_t sxor = (((uint32_t)(frow & 7)) << 4) ^ ((uint32_t)(lane >> 4) << 4);
    uint32_t QA[4], QB[2];
#pragma unroll
    for (int mt = 0; mt < 4; mt++)
        QA[mt] = sb + (wm * 64 + mt * 16 + frow) * 128 + sxor;
#pragma unroll
    for (int p = 0; p < 2; p++)
        QB[p] = sb + A_BYTES + (wn * 32 + p * 16 + frow) * 128 + sxor;

    float acc[4][4][4];
#pragma unroll
    for (int i = 0; i < 4; i++)
#pragma unroll
        for (int j = 0; j < 4; j++)
#pragma unroll
            for (int q = 0; q < 4; q++) acc[i][j][q] = 0.0f;

    const int kIters = Ktot / BK;

    // Issues loads for the NEXT sequential k-chunk; pointers self-advance.
    auto load_stage = [&](int buf) {
        const uint32_t sbase = sb + buf * STAGE_BYTES;
#pragma unroll
        for (int p = 0; p < 4; p++) {
            cp16(sbase + soff[p], pA[p]);
            cp16(sbase + A_BYTES + soff[p], pB[p]);
            pA[p] += BK;
            pB[p] += BK;
        }
    };

    // prologue: stages 0 and 1 (kIters >= 2 always here)
    load_stage(0); cp_commit();
    load_stage(1); cp_commit();

    int nbuf = 2;   // next stage buffer to fill
    int cbuf = 0;   // stage buffer QA/QB currently point at
    for (int it = 0; it < kIters; it++) {
        cp_wait1();
        // Single barrier: all warps done reading buffer (it-1)%3 == nbuf before refill.
        __syncthreads();

        if (it + 2 < kIters) load_stage(nbuf);
        cp_commit();
        nbuf = (nbuf + 1 == 3) ? 0 : nbuf + 1;

#pragma unroll
        for (int ks = 0; ks < 4; ks++) {            // 4 x k16 steps = K64
            const uint32_t kx = (uint32_t)ks << 5;  // immediate after unroll
            uint32_t a[4][4];
#pragma unroll
            for (int mt = 0; mt < 4; mt++)
                ldsm4(a[mt][0], a[mt][1], a[mt][2], a[mt][3], QA[mt] ^ kx);
            uint32_t b[2][4];
#pragma unroll
            for (int p = 0; p < 2; p++)
                ldsm4(b[p][0], b[p][1], b[p][2], b[p][3], QB[p] ^ kx);
#pragma unroll
            for (int mt = 0; mt < 4; mt++)
#pragma unroll
                for (int nt = 0; nt < 4; nt++) {
                    const int p = nt >> 1, o = nt & 1;
                    mma_f16(acc[mt][nt], a[mt], b[p][o], b[p][2 + o]);
                }
        }

        // advance QA/QB to the next stage in place (no extra live registers)
        const uint32_t dso = (cbuf == 2) ? (uint32_t)(-2 * STAGE_BYTES)
                                         : (uint32_t)STAGE_BYTES;
        cbuf = (cbuf + 1 == 3) ? 0 : cbuf + 1;
#pragma unroll
        for (int mt = 0; mt < 4; mt++) QA[mt] += dso;
#pragma unroll
        for (int p = 0; p < 2; p++) QB[p] += dso;
    }

    // ---- epilogue ----
    const int g = lane >> 2;
    const int cpair = (lane & 3) * 2;
#pragma unroll
    for (int mt = 0; mt < 4; mt++) {
        const long long r0 = rowBase + wm * 64 + mt * 16 + g;
        const long long r1 = r0 + 8;
        float rb0 = 0.f, rb1 = 0.f;
        if (biasMode == 2) { rb0 = bias[r0]; rb1 = bias[r1]; }
#pragma unroll
        for (int nt = 0; nt < 4; nt++) {
            const int col = colBase + wn * 32 + nt * 8 + cpair;
            float bx = 0.f, by = 0.f;
            if (biasMode == 1) { bx = bias[col]; by = bias[col + 1]; }
            float2 v0, v1;
            v0.x = acc[mt][nt][0] * alpha + bx + rb0;
            v0.y = acc[mt][nt][1] * alpha + by + rb0;
            v1.x = acc[mt][nt][2] * alpha + bx + rb1;
            v1.y = acc[mt][nt][3] * alpha + by + rb1;
            if (HALF_OUT) {
                __half* Cb = (__half*)Cv;
                *reinterpret_cast<__half2*>(Cb + r0 * Ntot + col) = __floats2half2_rn(v0.x, v0.y);
                *reinterpret_cast<__half2*>(Cb + r1 * Ntot + col) = __floats2half2_rn(v1.x, v1.y);
            } else {
                float* Cb = (float*)Cv;
                *reinterpret_cast<float2*>(Cb + r0 * Ntot + col) = v0;
                *reinterpret_cast<float2*>(Cb + r1 * Ntot + col) = v1;
            }
        }
    }
}

// ======= merged QKV projection: 1536 linear CTAs =======
__global__ void __launch_bounds__(256, 2) proj_kernel(
    const __half* __restrict__ x16, const __half* __restrict__ W16,
    const float* __restrict__ bq, const float* __restrict__ bk, const float* __restrict__ bv,
    __half* __restrict__ Q16, __half* __restrict__ K16, __half* __restrict__ Vt16)
{
    extern __shared__ __align__(1024) char smem[];
    const uint32_t sb = smem_u32(smem);
    const long long SD = (long long)Ss * Dd;
    const long long DD = (long long)Dd * Dd;

    const int cta = blockIdx.x;
    if (cta < 1024) {
        const int z = cta >> 9;
        const int rem = cta & 511;
        const int y = rem >> 3, x = rem & 7;
        gemm_body<true>(x16 + (long long)y * BM * Dd,
                        W16 + z * DD + (long long)x * BN * Dd,
                        z ? bk : bq, 1,
                        z ? K16 : Q16, Dd, Dd, 1.0f, y * BM, x * BN, sb);
    } else {
        const int i = cta - 1024;
        const int bz = i >> 7;
        const int rem = i & 127;
        const int y = rem >> 4, x = rem & 15;
        gemm_body<true>(W16 + 2 * DD + (long long)y * BM * Dd,
                        x16 + bz * SD + (long long)x * BN * Dd,
                        bv, 2,
                        Vt16 + bz * SD, Ss, Dd, 1.0f, y * BM, x * BN, sb);
    }
}

// ======= batched GEMM (scores / PV), fp32 out, no bias =======
__global__ void __launch_bounds__(256, 2) bgemm_kernel(
    const __half* __restrict__ A, const __half* __restrict__ Bm,
    float* __restrict__ C, int Ntot, int Ktot, float alpha,
    long long sA, long long sB, long long sC)
{
    extern __shared__ __align__(1024) char smem[];
    const uint32_t sb = smem_u32(smem);
    const int bz = blockIdx.z;
    gemm_body<false>(A + bz * sA + (long long)blockIdx.y * BM * Ktot,
                     Bm + bz * sB + (long long)blockIdx.x * BN * Ktot,
                     nullptr, 0,
                     C + bz * sC, Ntot, Ktot, alpha,
                     blockIdx.y * BM, blockIdx.x * BN, sb);
}

// ---------------- merged fp32 -> fp16 convert (x and 3 weights) ----------------
__global__ void cvt_all_kernel(const float* __restrict__ x,
                               const float* __restrict__ wq, const float* __restrict__ wk,
                               const float* __restrict__ wv,
                               __half* __restrict__ x16, __half* __restrict__ W16)
{
    const int b = blockIdx.x;
    const int tid = threadIdx.x;
    const float* src;
    __half* dst;
    int i;
    if (b < 8192) {                 // x: 2097152 float4
        src = x; dst = x16; i = b * 256 + tid;
    } else {                        // weights: 262144 float4 each
        const int wb = b - 8192;
        const int w = wb >> 10;     // 0..2
        src = (w == 0) ? wq : (w == 1) ? wk : wv;
        dst = W16 + (long long)w * Dd * Dd;
        i = (wb & 1023) * 256 + tid;
    }
    const float4 v = reinterpret_cast<const float4*>(src)[i];
    __half2* o = reinterpret_cast<__half2*>(dst);
    o[2 * i]     = __floats2half2_rn(v.x, v.y);
    o[2 * i + 1] = __floats2half2_rn(v.z, v.w);
}

// ------- row softmax over S=2048: reads fp32 scores, writes fp16 P -------
__global__ void __launch_bounds__(256) softmax_kernel(const float* __restrict__ S32,
                                                      __half* __restrict__ P16)
{
    const float* row = S32 + (long long)blockIdx.x * Ss;
    __half* orow = P16 + (long long)blockIdx.x * Ss;
    const int tid = threadIdx.x;
    const int w = tid >> 5, l = tid & 31;

    float v[8];
    float m = -1e30f;
#pragma unroll
    for (int i = 0; i < 8; i++) { v[i] = row[tid + i * 256]; m = fmaxf(m, v[i]); }
#pragma unroll
    for (int o = 16; o > 0; o >>= 1) m = fmaxf(m, __shfl_xor_sync(0xFFFFFFFFu, m, o));

    __shared__ float smax[8], ssum[8];
    if (l == 0) smax[w] = m;
    __syncthreads();
    m = smax[0];
#pragma unroll
    for (int i = 1; i < 8; i++) m = fmaxf(m, smax[i]);

    float s = 0.0f;
#pragma unroll
    for (int i = 0; i < 8; i++) { v[i] = __expf(v[i] - m); s += v[i]; }
#pragma unroll
    for (int o = 16; o > 0; o >>= 1) s += __shfl_xor_sync(0xFFFFFFFFu, s, o);
    if (l == 0) ssum[w] = s;
    __syncthreads();
    float tot = 0.0f;
#pragma unroll
    for (int i = 0; i < 8; i++) tot += ssum[i];
    const float inv = 1.0f / tot;
#pragma unroll
    for (int i = 0; i < 8; i++) orow[tid + i * 256] = __float2half_rn(v[i] * inv);
}

// ---------------- host ----------------
extern "C" void kernel_launch(void* const* d_in, const int* in_sizes, int n_in,
                              void* d_out, int out_size)
{
    const float* x  = (const float*)d_in[0];
    const float* Wq = (const float*)d_in[1];
    const float* bq = (const float*)d_in[2];
    const float* Wk = (const float*)d_in[3];
    const float* bk = (const float*)d_in[4];
    const float* Wv = (const float*)d_in[5];
    const float* bv = (const float*)d_in[6];
    float* out = (float*)d_out;

    __half *x16, *W16, *Q16, *K16, *Vt16, *P16;
    float* P32;
    cudaGetSymbolAddress((void**)&x16, g_x16);
    cudaGetSymbolAddress((void**)&W16, g_W16);
    cudaGetSymbolAddress((void**)&Q16, g_Q16);
    cudaGetSymbolAddress((void**)&K16, g_K16);
    cudaGetSymbolAddress((void**)&Vt16, g_Vt16);
    cudaGetSymbolAddress((void**)&P32, g_P32);
    cudaGetSymbolAddress((void**)&P16, g_P16);

    cudaFuncSetAttribute((const void*)proj_kernel,
                         cudaFuncAttributeMaxDynamicSharedMemorySize, SMEM_BYTES);
    cudaFuncSetAttribute((const void*)bgemm_kernel,
                         cudaFuncAttributeMaxDynamicSharedMemorySize, SMEM_BYTES);

    // 0) one merged convert launch (x + 3 weights)
    cvt_all_kernel<<<8192 + 3072, 256>>>(x, Wq, Wk, Wv, x16, W16);

    const long long SD = (long long)Ss * Dd;
    const long long SS2 = (long long)Ss * Ss;

    // 1) merged Q/K/Vt projections: one 1536-CTA launch
    proj_kernel<<<1536, 256, SMEM_BYTES>>>(x16, W16, bq, bk, bv, Q16, K16, Vt16);

    // 2) scores = Q @ K^T / 32 -> fp32
    const dim3 g2(Ss / BN, Ss / BM, Bb);
    bgemm_kernel<<<g2, 256, SMEM_BYTES>>>(Q16, K16, P32, Ss, Dd, 0.03125f, SD, SD, SS2);

    // 3) softmax fp32 -> fp16 P
    softmax_kernel<<<Bb * Ss, 256>>>(P32, P16);

    // 4) out = P16 @ Vt16^T -> fp32
    const dim3 g3(Dd / BN, Ss / BM, Bb);
    bgemm_kernel<<<g3, 256, SMEM_BYTES>>>(P16, Vt16, out, Dd, Ss, 1.0f, SS2, SD, SD);
}

// round 10
// speedup vs baseline: 1.0604x; 1.0492x over previous
#include <cuda_runtime.h>
#include <cuda_fp16.h>
#include <cstdint>

#define Bb 4
#define Ss 2048
#define Dd 1024

#define BM 128
#define BN 128
#define BK 64                                  // fp16: 64 * 2B = 128B per row
#define A_BYTES (BM * 128)                     // 16KB
#define STAGE_BYTES (2 * A_BYTES)              // 32KB
#define SMEM_BYTES (3 * STAGE_BYTES)           // 96KB, 3 stages

// ---------------- device scratch (allocation-free rule) ----------------
__device__ __align__(1024) __half g_x16[Bb * Ss * Dd];
__device__ __align__(1024) __half g_W16[3 * Dd * Dd];
__device__ __align__(1024) __half g_Q16[Bb * Ss * Dd];
__device__ __align__(1024) __half g_K16[Bb * Ss * Dd];
__device__ __align__(1024) __half g_Vt16[Bb * Ss * Dd];
__device__ __align__(1024) __half g_P16[Bb * Ss * Ss];
__device__ float g_rowinv[Bb * Ss];

// ---------------- helpers ----------------
__device__ __forceinline__ uint32_t smem_u32(const void* p) {
    uint32_t a;
    asm("{ .reg .u64 t; cvta.to.shared.u64 t, %1; cvt.u32.u64 %0, t; }" : "=r"(a) : "l"(p));
    return a;
}
__device__ __forceinline__ void cp16(uint32_t dst, const void* src) {
    asm volatile("cp.async.cg.shared.global [%0], [%1], 16;" :: "r"(dst), "l"(src));
}
__device__ __forceinline__ void cp_commit() {
    asm volatile("cp.async.commit_group;" ::: "memory");
}
__device__ __forceinline__ void cp_wait1() {
    asm volatile("cp.async.wait_group 1;" ::: "memory");
}
__device__ __forceinline__ void ldsm4(uint32_t& r0, uint32_t& r1, uint32_t& r2, uint32_t& r3,
                                      uint32_t addr) {
    asm volatile("ldmatrix.sync.aligned.m8n8.x4.shared.b16 {%0,%1,%2,%3}, [%4];"
                 : "=r"(r0), "=r"(r1), "=r"(r2), "=r"(r3) : "r"(addr));
}
__device__ __forceinline__ void mma_f16(float* c, const uint32_t* a, uint32_t b0, uint32_t b1) {
    asm volatile(
        "mma.sync.aligned.m16n8k16.row.col.f32.f16.f16.f32 "
        "{%0,%1,%2,%3}, {%4,%5,%6,%7}, {%8,%9}, {%0,%1,%2,%3};"
        : "+f"(c[0]), "+f"(c[1]), "+f"(c[2]), "+f"(c[3])
        : "r"(a[0]), "r"(a[1]), "r"(a[2]), "r"(a[3]), "r"(b0), "r"(b1));
}

// ======= shared fp16 mma.sync GEMM body (mainloop verbatim from the 381us R7) =======
// EPI: 0 = fp32 out, alpha only
//      1 = fp16 out, alpha + per-column bias
//      2 = fp16 out, alpha + per-row bias
//      3 = fp16 out, exp(alpha*s) * 2^-4       (unnormalized softmax numerator)
//      4 = fp32 out, acc * rowscale[row]       (PV normalize; bias = rowscale)
template <int EPI>
__device__ __forceinline__ void gemm_body(
    const __half* __restrict__ Ab, const __half* __restrict__ Bg0,
    const float* __restrict__ bias,
    void* __restrict__ Cv, int Ntot, int Ktot, float alpha,
    int rowBase, int colBase, uint32_t sb)
{
    const int tid = threadIdx.x;
    const int lane = tid & 31;
    const int wid = tid >> 5;
    const int wm = wid & 1;        // 2 warps in M (64 rows each)
    const int wn = wid >> 1;       // 4 warps in N (32 cols each)

    // -------- loader precompute --------
    const int lr = tid >> 3;       // 0..31
    const int lc = tid & 7;        // 0..7
    uint32_t soff[4];
    const __half* pA[4];
    const __half* pB[4];
#pragma unroll
    for (int p = 0; p < 4; p++) {
        const int row = lr + 32 * p;
        soff[p] = row * 128 + ((uint32_t)(lc ^ (row & 7)) << 4);
        pA[p] = Ab + (long long)row * Ktot + lc * 8;
        pB[p] = Bg0 + (long long)row * Ktot + lc * 8;
    }

    const int frow = lane & 15;
    const int fkc = lane >> 4;

    float acc[4][4][4];
#pragma unroll
    for (int i = 0; i < 4; i++)
#pragma unroll
        for (int j = 0; j < 4; j++)
#pragma unroll
            for (int q = 0; q < 4; q++) acc[i][j][q] = 0.0f;

    const int kIters = Ktot / BK;

    auto load_stage = [&](int buf) {
        const uint32_t sbase = sb + buf * STAGE_BYTES;
#pragma unroll
        for (int p = 0; p < 4; p++) {
            cp16(sbase + soff[p], pA[p]);
            cp16(sbase + A_BYTES + soff[p], pB[p]);
            pA[p] += BK;
            pB[p] += BK;
        }
    };

    load_stage(0); cp_commit();
    load_stage(1); cp_commit();

    int arow[4], brow[2];
#pragma unroll
    for (int mt = 0; mt < 4; mt++) arow[mt] = wm * 64 + mt * 16 + frow;
#pragma unroll
    for (int p = 0; p < 2; p++) brow[p] = wn * 32 + p * 16 + frow;

    int nbuf = 2;
    int cbuf = 0;
    for (int it = 0; it < kIters; it++) {
        cp_wait1();
        __syncthreads();

        if (it + 2 < kIters) load_stage(nbuf);
        cp_commit();
        nbuf = (nbuf + 1 == 3) ? 0 : nbuf + 1;

        const uint32_t As = sb + cbuf * STAGE_BYTES;
        const uint32_t Bs = As + A_BYTES;
        cbuf = (cbuf + 1 == 3) ? 0 : cbuf + 1;

#pragma unroll
        for (int ks = 0; ks < 4; ks++) {            // 4 x k16 steps = K64
            const int chunk = 2 * ks + fkc;
            uint32_t a[4][4];
#pragma unroll
            for (int mt = 0; mt < 4; mt++) {
                const uint32_t ad = As + arow[mt] * 128 +
                                    ((uint32_t)(chunk ^ (arow[mt] & 7)) << 4);
                ldsm4(a[mt][0], a[mt][1], a[mt][2], a[mt][3], ad);
            }
            uint32_t b[2][4];
#pragma unroll
            for (int p = 0; p < 2; p++) {
                const uint32_t bd = Bs + brow[p] * 128 +
                                    ((uint32_t)(chunk ^ (brow[p] & 7)) << 4);
                ldsm4(b[p][0], b[p][1], b[p][2], b[p][3], bd);
            }
#pragma unroll
            for (int mt = 0; mt < 4; mt++)
#pragma unroll
                for (int nt = 0; nt < 4; nt++) {
                    const int p = nt >> 1, o = nt & 1;
                    mma_f16(acc[mt][nt], a[mt], b[p][o], b[p][2 + o]);
                }
        }
    }

    // ---- epilogue ----
    const int g = lane >> 2;
    const int cpair = (lane & 3) * 2;
#pragma unroll
    for (int mt = 0; mt < 4; mt++) {
        const long long r0 = rowBase + wm * 64 + mt * 16 + g;
        const long long r1 = r0 + 8;
        float rb0 = 0.f, rb1 = 0.f;
        if (EPI == 2) { rb0 = bias[r0]; rb1 = bias[r1]; }
        if (EPI == 4) { rb0 = bias[r0]; rb1 = bias[r1]; }   // rowscale
#pragma unroll
        for (int nt = 0; nt < 4; nt++) {
            const int col = colBase + wn * 32 + nt * 8 + cpair;
            float v00 = acc[mt][nt][0] * alpha;
            float v01 = acc[mt][nt][1] * alpha;
            float v10 = acc[mt][nt][2] * alpha;
            float v11 = acc[mt][nt][3] * alpha;
            if (EPI == 1) {
                const float bx = bias[col], by = bias[col + 1];
                v00 += bx; v01 += by; v10 += bx; v11 += by;
            }
            if (EPI == 2) { v00 += rb0; v01 += rb0; v10 += rb1; v11 += rb1; }
            if (EPI == 3) {
                v00 = __expf(v00) * 0.0625f; v01 = __expf(v01) * 0.0625f;
                v10 = __expf(v10) * 0.0625f; v11 = __expf(v11) * 0.0625f;
            }
            if (EPI == 4) { v00 *= rb0; v01 *= rb0; v10 *= rb1; v11 *= rb1; }
            if (EPI == 1 || EPI == 2 || EPI == 3) {
                __half* Cb = (__half*)Cv;
                *reinterpret_cast<__half2*>(Cb + r0 * Ntot + col) = __floats2half2_rn(v00, v01);
                *reinterpret_cast<__half2*>(Cb + r1 * Ntot + col) = __floats2half2_rn(v10, v11);
            } else {
                float* Cb = (float*)Cv;
                *reinterpret_cast<float2*>(Cb + r0 * Ntot + col) = make_float2(v00, v01);
                *reinterpret_cast<float2*>(Cb + r1 * Ntot + col) = make_float2(v10, v11);
            }
        }
    }
}

// ======= merged QKV projection: 1536 linear CTAs =======
__global__ void __launch_bounds__(256, 2) proj_kernel(
    const __half* __restrict__ x16, const __half* __restrict__ W16,
    const float* __restrict__ bq, const float* __restrict__ bk, const float* __restrict__ bv,
    __half* __restrict__ Q16, __half* __restrict__ K16, __half* __restrict__ Vt16)
{
    extern __shared__ __align__(1024) char smem[];
    const uint32_t sb = smem_u32(smem);
    const long long SD = (long long)Ss * Dd;
    const long long DD = (long long)Dd * Dd;

    const int cta = blockIdx.x;
    if (cta < 1024) {
        const int z = cta >> 9;
        const int rem = cta & 511;
        const int y = rem >> 3, x = rem & 7;
        gemm_body<1>(x16 + (long long)y * BM * Dd,
                     W16 + z * DD + (long long)x * BN * Dd,
                     z ? bk : bq,
                     z ? K16 : Q16, Dd, Dd, 1.0f, y * BM, x * BN, sb);
    } else {
        const int i = cta - 1024;
        const int bz = i >> 7;
        const int rem = i & 127;
        const int y = rem >> 4, x = rem & 15;
        gemm_body<2>(W16 + 2 * DD + (long long)y * BM * Dd,
                     x16 + bz * SD + (long long)x * BN * Dd,
                     bv,
                     Vt16 + bz * SD, Ss, Dd, 1.0f, y * BM, x * BN, sb);
    }
}

// ======= scores GEMM: P16 = exp(Q K^T / 32) * 2^-4  (unnormalized) =======
__global__ void __launch_bounds__(256, 2) scores_kernel(
    const __half* __restrict__ Q, const __half* __restrict__ K,
    __half* __restrict__ P)
{
    extern __shared__ __align__(1024) char smem[];
    const uint32_t sb = smem_u32(smem);
    const long long SD = (long long)Ss * Dd;
    const long long SS2 = (long long)Ss * Ss;
    const int bz = blockIdx.z;
    gemm_body<3>(Q + bz * SD + (long long)blockIdx.y * BM * Dd,
                 K + bz * SD + (long long)blockIdx.x * BN * Dd,
                 nullptr,
                 P + bz * SS2, Ss, Dd, 0.03125f,
                 blockIdx.y * BM, blockIdx.x * BN, sb);
}

// ======= PV GEMM: out = (P16 @ Vt^T) * rowinv[row] =======
__global__ void __launch_bounds__(256, 2) pv_kernel(
    const __half* __restrict__ P, const __half* __restrict__ Vt,
    const float* __restrict__ rowinv, float* __restrict__ out)
{
    extern __shared__ __align__(1024) char smem[];
    const uint32_t sb = smem_u32(smem);
    const long long SD = (long long)Ss * Dd;
    const long long SS2 = (long long)Ss * Ss;
    const int bz = blockIdx.z;
    gemm_body<4>(P + bz * SS2 + (long long)blockIdx.y * BM * Ss,
                 Vt + bz * SD + (long long)blockIdx.x * BN * Ss,
                 rowinv + bz * Ss,
                 out + bz * SD, Dd, Ss, 1.0f,
                 blockIdx.y * BM, blockIdx.x * BN, sb);
}

// ---------------- merged fp32 -> fp16 convert (x and 3 weights) ----------------
__global__ void cvt_all_kernel(const float* __restrict__ x,
                               const float* __restrict__ wq, const float* __restrict__ wk,
                               const float* __restrict__ wv,
                               __half* __restrict__ x16, __half* __restrict__ W16)
{
    const int b = blockIdx.x;
    const int tid = threadIdx.x;
    const float* src;
    __half* dst;
    int i;
    if (b < 8192) {                 // x: 2097152 float4
        src = x; dst = x16; i = b * 256 + tid;
    } else {                        // weights: 262144 float4 each
        const int wb = b - 8192;
        const int w = wb >> 10;     // 0..2
        src = (w == 0) ? wq : (w == 1) ? wk : wv;
        dst = W16 + (long long)w * Dd * Dd;
        i = (wb & 1023) * 256 + tid;
    }
    const float4 v = reinterpret_cast<const float4*>(src)[i];
    __half2* o = reinterpret_cast<__half2*>(dst);
    o[2 * i]     = __floats2half2_rn(v.x, v.y);
    o[2 * i + 1] = __floats2half2_rn(v.z, v.w);
}

// ------- row sums of P16 (post-rounding), store reciprocal -------
__global__ void __launch_bounds__(256) rowsum_kernel(const __half* __restrict__ P16,
                                                     float* __restrict__ rowinv)
{
    const __half2* row = reinterpret_cast<const __half2*>(P16 + (long long)blockIdx.x * Ss);
    const int tid = threadIdx.x;
    const int w = tid >> 5, l = tid & 31;

    float s = 0.0f;
#pragma unroll
    for (int i = 0; i < 4; i++) {
        const float2 f = __half22float2(row[tid + i * 256]);
        s += f.x + f.y;
    }
#pragma unroll
    for (int o = 16; o > 0; o >>= 1) s += __shfl_xor_sync(0xFFFFFFFFu, s, o);

    __shared__ float ssum[8];
    if (l == 0) ssum[w] = s;
    __syncthreads();
    if (tid == 0) {
        float tot = 0.0f;
#pragma unroll
        for (int i = 0; i < 8; i++) tot += ssum[i];
        rowinv[blockIdx.x] = 1.0f / tot;
    }
}

// ---------------- host ----------------
extern "C" void kernel_launch(void* const* d_in, const int* in_sizes, int n_in,
                              void* d_out, int out_size)
{
    const float* x  = (const float*)d_in[0];
    const float* Wq = (const float*)d_in[1];
    const float* bq = (const float*)d_in[2];
    const float* Wk = (const float*)d_in[3];
    const float* bk = (const float*)d_in[4];
    const float* Wv = (const float*)d_in[5];
    const float* bv = (const float*)d_in[6];
    float* out = (float*)d_out;

    __half *x16, *W16, *Q16, *K16, *Vt16, *P16;
    float* rowinv;
    cudaGetSymbolAddress((void**)&x16, g_x16);
    cudaGetSymbolAddress((void**)&W16, g_W16);
    cudaGetSymbolAddress((void**)&Q16, g_Q16);
    cudaGetSymbolAddress((void**)&K16, g_K16);
    cudaGetSymbolAddress((void**)&Vt16, g_Vt16);
    cudaGetSymbolAddress((void**)&P16, g_P16);
    cudaGetSymbolAddress((void**)&rowinv, g_rowinv);

    cudaFuncSetAttribute((const void*)proj_kernel,
                         cudaFuncAttributeMaxDynamicSharedMemorySize, SMEM_BYTES);
    cudaFuncSetAttribute((const void*)scores_kernel,
                         cudaFuncAttributeMaxDynamicSharedMemorySize, SMEM_BYTES);
    cudaFuncSetAttribute((const void*)pv_kernel,
                         cudaFuncAttributeMaxDynamicSharedMemorySize, SMEM_BYTES);

    // 0) one merged convert launch (x + 3 weights)
    cvt_all_kernel<<<8192 + 3072, 256>>>(x, Wq, Wk, Wv, x16, W16);

    // 1) merged Q/K/Vt projections: one 1536-CTA launch
    proj_kernel<<<1536, 256, SMEM_BYTES>>>(x16, W16, bq, bk, bv, Q16, K16, Vt16);

    // 2) P = exp(Q K^T / 32) * 2^-4 (fp16, unnormalized)
    const dim3 g2(Ss / BN, Ss / BM, Bb);
    scores_kernel<<<g2, 256, SMEM_BYTES>>>(Q16, K16, P16);

    // 3) row sums -> reciprocals
    rowsum_kernel<<<Bb * Ss, 256>>>(P16, rowinv);

    // 4) out = (P @ Vt^T) * rowinv
    const dim3 g3(Dd / BN, Ss / BM, Bb);
    pv_kernel<<<g3, 256, SMEM_BYTES>>>(P16, Vt16, rowinv, out);
}

// round 11
// speedup vs baseline: 1.0754x; 1.0141x over previous
#include <cuda_runtime.h>
#include <cuda_fp16.h>
#include <cstdint>

#define Bb 4
#define Ss 2048
#define Dd 1024

#define BM 128
#define BN 128
#define BK 64                                  // fp16: 64 * 2B = 128B per row
#define A_BYTES (BM * 128)                     // 16KB
#define STAGE_BYTES (2 * A_BYTES)              // 32KB
#define SMEM_BYTES (3 * STAGE_BYTES)           // 96KB, 3 stages
#define NT 128                                 // threads per GEMM CTA (4 warps, 2x2)

// ---------------- device scratch (allocation-free rule) ----------------
__device__ __align__(1024) __half g_x16[Bb * Ss * Dd];
__device__ __align__(1024) __half g_W16[3 * Dd * Dd];
__device__ __align__(1024) __half g_Q16[Bb * Ss * Dd];
__device__ __align__(1024) __half g_K16[Bb * Ss * Dd];
__device__ __align__(1024) __half g_Vt16[Bb * Ss * Dd];
__device__ __align__(1024) __half g_P16[Bb * Ss * Ss];
__device__ float g_rowsum[Bb * Ss];

// ---------------- helpers ----------------
__device__ __forceinline__ uint32_t smem_u32(const void* p) {
    uint32_t a;
    asm("{ .reg .u64 t; cvta.to.shared.u64 t, %1; cvt.u32.u64 %0, t; }" : "=r"(a) : "l"(p));
    return a;
}
__device__ __forceinline__ void cp16(uint32_t dst, const void* src) {
    asm volatile("cp.async.cg.shared.global [%0], [%1], 16;" :: "r"(dst), "l"(src));
}
__device__ __forceinline__ void cp_commit() {
    asm volatile("cp.async.commit_group;" ::: "memory");
}
__device__ __forceinline__ void cp_wait1() {
    asm volatile("cp.async.wait_group 1;" ::: "memory");
}
__device__ __forceinline__ void ldsm4(uint32_t& r0, uint32_t& r1, uint32_t& r2, uint32_t& r3,
                                      uint32_t addr) {
    asm volatile("ldmatrix.sync.aligned.m8n8.x4.shared.b16 {%0,%1,%2,%3}, [%4];"
                 : "=r"(r0), "=r"(r1), "=r"(r2), "=r"(r3) : "r"(addr));
}
__device__ __forceinline__ void mma_f16(float* c, const uint32_t* a, uint32_t b0, uint32_t b1) {
    asm volatile(
        "mma.sync.aligned.m16n8k16.row.col.f32.f16.f16.f32 "
        "{%0,%1,%2,%3}, {%4,%5,%6,%7}, {%8,%9}, {%0,%1,%2,%3};"
        : "+f"(c[0]), "+f"(c[1]), "+f"(c[2]), "+f"(c[3])
        : "r"(a[0]), "r"(a[1]), "r"(a[2]), "r"(a[3]), "r"(b0), "r"(b1));
}

// ======= fp16 mma.sync GEMM body: 128 threads, 4 warps 2(M)x2(N), warp tile 64x64 =======
// Rationale: per CTA per k-iter LDSM traffic drops 96KB -> 64KB vs the 8-warp/64x32
// config, taking smem crossbar (was 2048 cyc, tied with HMMA floor) off the critical
// path. 2 CTAs/SM preserved (96KB smem, regs < 256 under launch_bounds(128,2)).
// EPI: 1 = fp16 out, alpha + per-column bias
//      2 = fp16 out, alpha + per-row bias
//      3 = fp16 out, exp(alpha*s)*2^-4, fused row-sum atomicAdd into aux
//      4 = fp32 out, acc * (1/aux[row])          (PV normalize)
template <int EPI>
__device__ __forceinline__ void gemm_body(
    const __half* __restrict__ Ab, const __half* __restrict__ Bg0,
    const float* __restrict__ bias, float* __restrict__ aux,
    void* __restrict__ Cv, int Ntot, int Ktot, float alpha,
    int rowBase, int colBase, uint32_t sb)
{
    const int tid = threadIdx.x;
    const int lane = tid & 31;
    const int wid = tid >> 5;
    const int wm = wid & 1;        // 2 warps in M (64 rows each)
    const int wn = wid >> 1;       // 2 warps in N (64 cols each)

    // -------- loader precompute: 128 threads, 16 rows per pass, 8 passes/operand --------
    const int lr = tid >> 3;       // 0..15
    const int lc = tid & 7;        // 0..7
    // (lr + 16p) & 7 == lr & 7, so swizzle offset is pass-invariant:
    const uint32_t soff0 = lr * 128 + ((uint32_t)(lc ^ (lr & 7)) << 4);
    const int st16 = 16 * Ktot;    // element stride between passes
    const __half* pA = Ab + (long long)lr * Ktot + lc * 8;
    const __half* pB = Bg0 + (long long)lr * Ktot + lc * 8;

    const int frow = lane & 15;
    const int fkc = lane >> 4;

    float acc[4][8][4];
#pragma unroll
    for (int i = 0; i < 4; i++)
#pragma unroll
        for (int j = 0; j < 8; j++)
#pragma unroll
            for (int q = 0; q < 4; q++) acc[i][j][q] = 0.0f;

    const int kIters = Ktot / BK;

    auto load_stage = [&](int buf) {
        const uint32_t sbase = sb + buf * STAGE_BYTES + soff0;
#pragma unroll
        for (int p = 0; p < 8; p++) {
            cp16(sbase + p * 2048, pA + p * st16);
            cp16(sbase + A_BYTES + p * 2048, pB + p * st16);
        }
        pA += BK;
        pB += BK;
    };

    load_stage(0); cp_commit();
    load_stage(1); cp_commit();

    int arow[4], brow[4];
#pragma unroll
    for (int mt = 0; mt < 4; mt++) arow[mt] = wm * 64 + mt * 16 + frow;
#pragma unroll
    for (int p = 0; p < 4; p++) brow[p] = wn * 64 + p * 16 + frow;

    int nbuf = 2;
    int cbuf = 0;
    for (int it = 0; it < kIters; it++) {
        cp_wait1();
        __syncthreads();

        if (it + 2 < kIters) load_stage(nbuf);
        cp_commit();
        nbuf = (nbuf + 1 == 3) ? 0 : nbuf + 1;

        const uint32_t As = sb + cbuf * STAGE_BYTES;
        const uint32_t Bs = As + A_BYTES;
        cbuf = (cbuf + 1 == 3) ? 0 : cbuf + 1;

#pragma unroll
        for (int ks = 0; ks < 4; ks++) {            // 4 x k16 steps = K64
            const int chunk = 2 * ks + fkc;
            uint32_t a[4][4];
#pragma unroll
            for (int mt = 0; mt < 4; mt++) {
                const uint32_t ad = As + arow[mt] * 128 +
                                    ((uint32_t)(chunk ^ (arow[mt] & 7)) << 4);
                ldsm4(a[mt][0], a[mt][1], a[mt][2], a[mt][3], ad);
            }
            uint32_t b[4][4];
#pragma unroll
            for (int p = 0; p < 4; p++) {
                const uint32_t bd = Bs + brow[p] * 128 +
                                    ((uint32_t)(chunk ^ (brow[p] & 7)) << 4);
                ldsm4(b[p][0], b[p][1], b[p][2], b[p][3], bd);
            }
#pragma unroll
            for (int mt = 0; mt < 4; mt++)
#pragma unroll
                for (int nt = 0; nt < 8; nt++) {
                    const int p = nt >> 1, o = nt & 1;
                    mma_f16(acc[mt][nt], a[mt], b[p][o], b[p][2 + o]);
                }
        }
    }

    // ---- epilogue ----
    const int g = lane >> 2;
    const int cpair = (lane & 3) * 2;
#pragma unroll
    for (int mt = 0; mt < 4; mt++) {
        const long long r0 = rowBase + wm * 64 + mt * 16 + g;
        const long long r1 = r0 + 8;
        float rb0 = 0.f, rb1 = 0.f;
        if (EPI == 2) { rb0 = bias[r0]; rb1 = bias[r1]; }
        if (EPI == 4) { rb0 = 1.0f / aux[r0]; rb1 = 1.0f / aux[r1]; }
        float sum0 = 0.f, sum1 = 0.f;
#pragma unroll
        for (int nt = 0; nt < 8; nt++) {
            const int col = colBase + wn * 64 + nt * 8 + cpair;
            float v00 = acc[mt][nt][0] * alpha;
            float v01 = acc[mt][nt][1] * alpha;
            float v10 = acc[mt][nt][2] * alpha;
            float v11 = acc[mt][nt][3] * alpha;
            if (EPI == 1) {
                const float bx = bias[col], by = bias[col + 1];
                v00 += bx; v01 += by; v10 += bx; v11 += by;
            }
            if (EPI == 2) { v00 += rb0; v01 += rb0; v10 += rb1; v11 += rb1; }
            if (EPI == 3) {
                v00 = __expf(v00) * 0.0625f; v01 = __expf(v01) * 0.0625f;
                v10 = __expf(v10) * 0.0625f; v11 = __expf(v11) * 0.0625f;
                sum0 += v00 + v01; sum1 += v10 + v11;
            }
            if (EPI == 4) { v00 *= rb0; v01 *= rb0; v10 *= rb1; v11 *= rb1; }
            if (EPI == 4) {
                float* Cb = (float*)Cv;
                *reinterpret_cast<float2*>(Cb + r0 * Ntot + col) = make_float2(v00, v01);
                *reinterpret_cast<float2*>(Cb + r1 * Ntot + col) = make_float2(v10, v11);
            } else {
                __half* Cb = (__half*)Cv;
                *reinterpret_cast<__half2*>(Cb + r0 * Ntot + col) = __floats2half2_rn(v00, v01);
                *reinterpret_cast<__half2*>(Cb + r1 * Ntot + col) = __floats2half2_rn(v10, v11);
            }
        }
        if (EPI == 3) {
            // reduce across the 4 lanes of each quad (same row, different cpair)
            sum0 += __shfl_xor_sync(0xFFFFFFFFu, sum0, 1);
            sum0 += __shfl_xor_sync(0xFFFFFFFFu, sum0, 2);
            sum1 += __shfl_xor_sync(0xFFFFFFFFu, sum1, 1);
            sum1 += __shfl_xor_sync(0xFFFFFFFFu, sum1, 2);
            if ((lane & 3) == 0) {
                atomicAdd(aux + r0, sum0);
                atomicAdd(aux + r1, sum1);
            }
        }
    }
}

// ======= merged QKV projection: 1536 linear CTAs (128 threads each) =======
__global__ void __launch_bounds__(NT, 2) proj_kernel(
    const __half* __restrict__ x16, const __half* __restrict__ W16,
    const float* __restrict__ bq, const float* __restrict__ bk, const float* __restrict__ bv,
    __half* __restrict__ Q16, __half* __restrict__ K16, __half* __restrict__ Vt16)
{
    extern __shared__ __align__(1024) char smem[];
    const uint32_t sb = smem_u32(smem);
    const long long SD = (long long)Ss * Dd;
    const long long DD = (long long)Dd * Dd;

    const int cta = blockIdx.x;
    if (cta < 1024) {
        const int z = cta >> 9;
        const int rem = cta & 511;
        const int y = rem >> 3, x = rem & 7;
        gemm_body<1>(x16 + (long long)y * BM * Dd,
                     W16 + z * DD + (long long)x * BN * Dd,
                     z ? bk : bq, nullptr,
                     z ? K16 : Q16, Dd, Dd, 1.0f, y * BM, x * BN, sb);
    } else {
        const int i = cta - 1024;
        const int bz = i >> 7;
        const int rem = i & 127;
        const int y = rem >> 4, x = rem & 15;
        gemm_body<2>(W16 + 2 * DD + (long long)y * BM * Dd,
                     x16 + bz * SD + (long long)x * BN * Dd,
                     bv, nullptr,
                     Vt16 + bz * SD, Ss, Dd, 1.0f, y * BM, x * BN, sb);
    }
}

// ======= scores GEMM: P16 = exp(Q K^T / 32) * 2^-4, row sums fused via atomics =======
__global__ void __launch_bounds__(NT, 2) scores_kernel(
    const __half* __restrict__ Q, const __half* __restrict__ K,
    __half* __restrict__ P, float* __restrict__ rowsum)
{
    extern __shared__ __align__(1024) char smem[];
    const uint32_t sb = smem_u32(smem);
    const long long SD = (long long)Ss * Dd;
    const long long SS2 = (long long)Ss * Ss;
    const int bz = blockIdx.z;
    gemm_body<3>(Q + bz * SD + (long long)blockIdx.y * BM * Dd,
                 K + bz * SD + (long long)blockIdx.x * BN * Dd,
                 nullptr, rowsum + bz * Ss,
                 P + bz * SS2, Ss, Dd, 0.03125f,
                 blockIdx.y * BM, blockIdx.x * BN, sb);
}

// ======= PV GEMM: out = (P16 @ Vt^T) / rowsum[row] =======
__global__ void __launch_bounds__(NT, 2) pv_kernel(
    const __half* __restrict__ P, const __half* __restrict__ Vt,
    const float* __restrict__ rowsum, float* __restrict__ out)
{
    extern __shared__ __align__(1024) char smem[];
    const uint32_t sb = smem_u32(smem);
    const long long SD = (long long)Ss * Dd;
    const long long SS2 = (long long)Ss * Ss;
    const int bz = blockIdx.z;
    gemm_body<4>(P + bz * SS2 + (long long)blockIdx.y * BM * Ss,
                 Vt + bz * SD + (long long)blockIdx.x * BN * Ss,
                 nullptr, const_cast<float*>(rowsum) + bz * Ss,
                 out + bz * SD, Dd, Ss, 1.0f,
                 blockIdx.y * BM, blockIdx.x * BN, sb);
}

// ---------------- merged fp32 -> fp16 convert (x and 3 weights) ----------------
__global__ void cvt_all_kernel(const float* __restrict__ x,
                               const float* __restrict__ wq, const float* __restrict__ wk,
                               const float* __restrict__ wv,
                               __half* __restrict__ x16, __half* __restrict__ W16)
{
    const int b = blockIdx.x;
    const int tid = threadIdx.x;
    const float* src;
    __half* dst;
    int i;
    if (b < 8192) {                 // x: 2097152 float4
        src = x; dst = x16; i = b * 256 + tid;
    } else {                        // weights: 262144 float4 each
        const int wb = b - 8192;
        const int w = wb >> 10;     // 0..2
        src = (w == 0) ? wq : (w == 1) ? wk : wv;
        dst = W16 + (long long)w * Dd * Dd;
        i = (wb & 1023) * 256 + tid;
    }
    const float4 v = reinterpret_cast<const float4*>(src)[i];
    __half2* o = reinterpret_cast<__half2*>(dst);
    o[2 * i]     = __floats2half2_rn(v.x, v.y);
    o[2 * i + 1] = __floats2half2_rn(v.z, v.w);
}

// ---------------- host ----------------
extern "C" void kernel_launch(void* const* d_in, const int* in_sizes, int n_in,
                              void* d_out, int out_size)
{
    const float* x  = (const float*)d_in[0];
    const float* Wq = (const float*)d_in[1];
    const float* bq = (const float*)d_in[2];
    const float* Wk = (const float*)d_in[3];
    const float* bk = (const float*)d_in[4];
    const float* Wv = (const float*)d_in[5];
    const float* bv = (const float*)d_in[6];
    float* out = (float*)d_out;

    __half *x16, *W16, *Q16, *K16, *Vt16, *P16;
    float* rowsum;
    cudaGetSymbolAddress((void**)&x16, g_x16);
    cudaGetSymbolAddress((void**)&W16, g_W16);
    cudaGetSymbolAddress((void**)&Q16, g_Q16);
    cudaGetSymbolAddress((void**)&K16, g_K16);
    cudaGetSymbolAddress((void**)&Vt16, g_Vt16);
    cudaGetSymbolAddress((void**)&P16, g_P16);
    cudaGetSymbolAddress((void**)&rowsum, g_rowsum);

    cudaFuncSetAttribute((const void*)proj_kernel,
                         cudaFuncAttributeMaxDynamicSharedMemorySize, SMEM_BYTES);
    cudaFuncSetAttribute((const void*)scores_kernel,
                         cudaFuncAttributeMaxDynamicSharedMemorySize, SMEM_BYTES);
    cudaFuncSetAttribute((const void*)pv_kernel,
                         cudaFuncAttributeMaxDynamicSharedMemorySize, SMEM_BYTES);

    // 0) zero the fused row-sum accumulator; convert inputs to fp16
    cudaMemsetAsync(rowsum, 0, Bb * Ss * sizeof(float));
    cvt_all_kernel<<<8192 + 3072, 256>>>(x, Wq, Wk, Wv, x16, W16);

    // 1) merged Q/K/Vt projections: one 1536-CTA launch
    proj_kernel<<<1536, NT, SMEM_BYTES>>>(x16, W16, bq, bk, bv, Q16, K16, Vt16);

    // 2) P = exp(Q K^T / 32) * 2^-4 (fp16, unnormalized), row sums accumulated
    const dim3 g2(Ss / BN, Ss / BM, Bb);
    scores_kernel<<<g2, NT, SMEM_BYTES>>>(Q16, K16, P16, rowsum);

    // 3) out = (P @ Vt^T) / rowsum
    const dim3 g3(Dd / BN, Ss / BM, Bb);
    pv_kernel<<<g3, NT, SMEM_BYTES>>>(P16, Vt16, rowsum, out);
}

// round 12
// speedup vs baseline: 1.0772x; 1.0017x over previous
#include <cuda_runtime.h>
#include <cuda_fp16.h>
#include <cstdint>

#define Bb 4
#define Ss 2048
#define Dd 1024

#define BM 128
#define BN 128
#define BK 64                                  // fp16: 64 * 2B = 128B per row
#define A_BYTES (BM * 128)                     // 16KB
#define STAGE_BYTES (2 * A_BYTES)              // 32KB
#define SMEM_BYTES (3 * STAGE_BYTES)           // 96KB, 3 stages
#define NT 128                                 // threads per GEMM CTA (4 warps, 2x2)

// ---------------- device scratch (allocation-free rule) ----------------
__device__ __align__(1024) __half g_x16[Bb * Ss * Dd];
__device__ __align__(1024) __half g_W16[3 * Dd * Dd];
__device__ __align__(1024) __half g_Q16[Bb * Ss * Dd];
__device__ __align__(1024) __half g_K16[Bb * Ss * Dd];
__device__ __align__(1024) __half g_Vt16[Bb * Ss * Dd];
__device__ __align__(1024) __half g_P16[Bb * Ss * Ss];
__device__ float g_rowsum[Bb * Ss];

// ---------------- helpers ----------------
__device__ __forceinline__ uint32_t smem_u32(const void* p) {
    uint32_t a;
    asm("{ .reg .u64 t; cvta.to.shared.u64 t, %1; cvt.u32.u64 %0, t; }" : "=r"(a) : "l"(p));
    return a;
}
__device__ __forceinline__ void cp16(uint32_t dst, const void* src) {
    asm volatile("cp.async.cg.shared.global [%0], [%1], 16;" :: "r"(dst), "l"(src));
}
__device__ __forceinline__ void cp_commit() {
    asm volatile("cp.async.commit_group;" ::: "memory");
}
__device__ __forceinline__ void cp_wait1() {
    asm volatile("cp.async.wait_group 1;" ::: "memory");
}
__device__ __forceinline__ void ldsm4(uint32_t& r0, uint32_t& r1, uint32_t& r2, uint32_t& r3,
                                      uint32_t addr) {
    asm volatile("ldmatrix.sync.aligned.m8n8.x4.shared.b16 {%0,%1,%2,%3}, [%4];"
                 : "=r"(r0), "=r"(r1), "=r"(r2), "=r"(r3) : "r"(addr));
}
__device__ __forceinline__ void mma_f16(float* c, const uint32_t* a, uint32_t b0, uint32_t b1) {
    asm volatile(
        "mma.sync.aligned.m16n8k16.row.col.f32.f16.f16.f32 "
        "{%0,%1,%2,%3}, {%4,%5,%6,%7}, {%8,%9}, {%0,%1,%2,%3};"
        : "+f"(c[0]), "+f"(c[1]), "+f"(c[2]), "+f"(c[3])
        : "r"(a[0]), "r"(a[1]), "r"(a[2]), "r"(a[3]), "r"(b0), "r"(b1));
}

// ======= fp16 mma.sync GEMM body: 128 threads, 4 warps 2(M)x2(N), warp tile 64x64 =======
// Fragment double-buffering: ldsm for ks+1 issues before the ks mma block, hiding
// the ~29cyc LDS latency that 2-warps/SMSP occupancy cannot (R11 ncu: tensor=52%,
// issue=30% -> short-scoreboard stalls on LDSM->HMMA). Register cost +32 regs,
// safe under the 256-reg/thread ceiling of launch_bounds(128,2).
// EPI: 1 = fp16 out, alpha + per-column bias
//      2 = fp16 out, alpha + per-row bias
//      3 = fp16 out, exp(alpha*s)*2^-4, fused row-sum atomicAdd into aux
//      4 = fp32 out, acc * (1/aux[row])          (PV normalize)
template <int EPI>
__device__ __forceinline__ void gemm_body(
    const __half* __restrict__ Ab, const __half* __restrict__ Bg0,
    const float* __restrict__ bias, float* __restrict__ aux,
    void* __restrict__ Cv, int Ntot, int Ktot, float alpha,
    int rowBase, int colBase, uint32_t sb)
{
    const int tid = threadIdx.x;
    const int lane = tid & 31;
    const int wid = tid >> 5;
    const int wm = wid & 1;        // 2 warps in M (64 rows each)
    const int wn = wid >> 1;       // 2 warps in N (64 cols each)

    // -------- loader precompute: 128 threads, 16 rows per pass, 8 passes/operand --------
    const int lr = tid >> 3;       // 0..15
    const int lc = tid & 7;        // 0..7
    const uint32_t soff0 = lr * 128 + ((uint32_t)(lc ^ (lr & 7)) << 4);
    const int st16 = 16 * Ktot;    // element stride between passes
    const __half* pA = Ab + (long long)lr * Ktot + lc * 8;
    const __half* pB = Bg0 + (long long)lr * Ktot + lc * 8;

    const int frow = lane & 15;
    const int fkc = lane >> 4;

    float acc[4][8][4];
#pragma unroll
    for (int i = 0; i < 4; i++)
#pragma unroll
        for (int j = 0; j < 8; j++)
#pragma unroll
            for (int q = 0; q < 4; q++) acc[i][j][q] = 0.0f;

    const int kIters = Ktot / BK;

    auto load_stage = [&](int buf) {
        const uint32_t sbase = sb + buf * STAGE_BYTES + soff0;
#pragma unroll
        for (int p = 0; p < 8; p++) {
            cp16(sbase + p * 2048, pA + p * st16);
            cp16(sbase + A_BYTES + p * 2048, pB + p * st16);
        }
        pA += BK;
        pB += BK;
    };

    load_stage(0); cp_commit();
    load_stage(1); cp_commit();

    int arow[4], brow[4];
#pragma unroll
    for (int mt = 0; mt < 4; mt++) arow[mt] = wm * 64 + mt * 16 + frow;
#pragma unroll
    for (int p = 0; p < 4; p++) brow[p] = wn * 64 + p * 16 + frow;

    int nbuf = 2;
    int cbuf = 0;
    for (int it = 0; it < kIters; it++) {
        cp_wait1();
        __syncthreads();

        if (it + 2 < kIters) load_stage(nbuf);
        cp_commit();
        nbuf = (nbuf + 1 == 3) ? 0 : nbuf + 1;

        const uint32_t As = sb + cbuf * STAGE_BYTES;
        const uint32_t Bs = As + A_BYTES;
        cbuf = (cbuf + 1 == 3) ? 0 : cbuf + 1;

        // fragment double buffers
        uint32_t af[2][4][4], bf[2][4][4];

        // prefetch ks = 0
        {
            const int chunk = fkc;
#pragma unroll
            for (int mt = 0; mt < 4; mt++) {
                const uint32_t ad = As + arow[mt] * 128 +
                                    ((uint32_t)(chunk ^ (arow[mt] & 7)) << 4);
                ldsm4(af[0][mt][0], af[0][mt][1], af[0][mt][2], af[0][mt][3], ad);
            }
#pragma unroll
            for (int p = 0; p < 4; p++) {
                const uint32_t bd = Bs + brow[p] * 128 +
                                    ((uint32_t)(chunk ^ (brow[p] & 7)) << 4);
                ldsm4(bf[0][p][0], bf[0][p][1], bf[0][p][2], bf[0][p][3], bd);
            }
        }

#pragma unroll
        for (int ks = 0; ks < 4; ks++) {            // 4 x k16 steps = K64
            const int cur = ks & 1;
            if (ks < 3) {                            // prefetch ks+1 before the mma block
                const int chunk = 2 * (ks + 1) + fkc;
                const int nxt = cur ^ 1;
#pragma unroll
                for (int mt = 0; mt < 4; mt++) {
                    const uint32_t ad = As + arow[mt] * 128 +
                                        ((uint32_t)(chunk ^ (arow[mt] & 7)) << 4);
                    ldsm4(af[nxt][mt][0], af[nxt][mt][1], af[nxt][mt][2], af[nxt][mt][3], ad);
                }
#pragma unroll
                for (int p = 0; p < 4; p++) {
                    const uint32_t bd = Bs + brow[p] * 128 +
                                        ((uint32_t)(chunk ^ (brow[p] & 7)) << 4);
                    ldsm4(bf[nxt][p][0], bf[nxt][p][1], bf[nxt][p][2], bf[nxt][p][3], bd);
                }
            }
#pragma unroll
            for (int mt = 0; mt < 4; mt++)
#pragma unroll
                for (int nt = 0; nt < 8; nt++) {
                    const int p = nt >> 1, o = nt & 1;
                    mma_f16(acc[mt][nt], af[cur][mt], bf[cur][p][o], bf[cur][p][2 + o]);
                }
        }
    }

    // ---- epilogue ----
    const int g = lane >> 2;
    const int cpair = (lane & 3) * 2;
#pragma unroll
    for (int mt = 0; mt < 4; mt++) {
        const long long r0 = rowBase + wm * 64 + mt * 16 + g;
        const long long r1 = r0 + 8;
        float rb0 = 0.f, rb1 = 0.f;
        if (EPI == 2) { rb0 = bias[r0]; rb1 = bias[r1]; }
        if (EPI == 4) { rb0 = 1.0f / aux[r0]; rb1 = 1.0f / aux[r1]; }
        float sum0 = 0.f, sum1 = 0.f;
#pragma unroll
        for (int nt = 0; nt < 8; nt++) {
            const int col = colBase + wn * 64 + nt * 8 + cpair;
            float v00 = acc[mt][nt][0] * alpha;
            float v01 = acc[mt][nt][1] * alpha;
            float v10 = acc[mt][nt][2] * alpha;
            float v11 = acc[mt][nt][3] * alpha;
            if (EPI == 1) {
                const float bx = bias[col], by = bias[col + 1];
                v00 += bx; v01 += by; v10 += bx; v11 += by;
            }
            if (EPI == 2) { v00 += rb0; v01 += rb0; v10 += rb1; v11 += rb1; }
            if (EPI == 3) {
                v00 = __expf(v00) * 0.0625f; v01 = __expf(v01) * 0.0625f;
                v10 = __expf(v10) * 0.0625f; v11 = __expf(v11) * 0.0625f;
                sum0 += v00 + v01; sum1 += v10 + v11;
            }
            if (EPI == 4) { v00 *= rb0; v01 *= rb0; v10 *= rb1; v11 *= rb1; }
            if (EPI == 4) {
                float* Cb = (float*)Cv;
                *reinterpret_cast<float2*>(Cb + r0 * Ntot + col) = make_float2(v00, v01);
                *reinterpret_cast<float2*>(Cb + r1 * Ntot + col) = make_float2(v10, v11);
            } else {
                __half* Cb = (__half*)Cv;
                *reinterpret_cast<__half2*>(Cb + r0 * Ntot + col) = __floats2half2_rn(v00, v01);
                *reinterpret_cast<__half2*>(Cb + r1 * Ntot + col) = __floats2half2_rn(v10, v11);
            }
        }
        if (EPI == 3) {
            sum0 += __shfl_xor_sync(0xFFFFFFFFu, sum0, 1);
            sum0 += __shfl_xor_sync(0xFFFFFFFFu, sum0, 2);
            sum1 += __shfl_xor_sync(0xFFFFFFFFu, sum1, 1);
            sum1 += __shfl_xor_sync(0xFFFFFFFFu, sum1, 2);
            if ((lane & 3) == 0) {
                atomicAdd(aux + r0, sum0);
                atomicAdd(aux + r1, sum1);
            }
        }
    }
}

// ======= merged QKV projection: 1536 linear CTAs (128 threads each) =======
__global__ void __launch_bounds__(NT, 2) proj_kernel(
    const __half* __restrict__ x16, const __half* __restrict__ W16,
    const float* __restrict__ bq, const float* __restrict__ bk, const float* __restrict__ bv,
    __half* __restrict__ Q16, __half* __restrict__ K16, __half* __restrict__ Vt16)
{
    extern __shared__ __align__(1024) char smem[];
    const uint32_t sb = smem_u32(smem);
    const long long SD = (long long)Ss * Dd;
    const long long DD = (long long)Dd * Dd;

    const int cta = blockIdx.x;
    if (cta < 1024) {
        const int z = cta >> 9;
        const int rem = cta & 511;
        const int y = rem >> 3, x = rem & 7;
        gemm_body<1>(x16 + (long long)y * BM * Dd,
                     W16 + z * DD + (long long)x * BN * Dd,
                     z ? bk : bq, nullptr,
                     z ? K16 : Q16, Dd, Dd, 1.0f, y * BM, x * BN, sb);
    } else {
        const int i = cta - 1024;
        const int bz = i >> 7;
        const int rem = i & 127;
        const int y = rem >> 4, x = rem & 15;
        gemm_body<2>(W16 + 2 * DD + (long long)y * BM * Dd,
                     x16 + bz * SD + (long long)x * BN * Dd,
                     bv, nullptr,
                     Vt16 + bz * SD, Ss, Dd, 1.0f, y * BM, x * BN, sb);
    }
}

// ======= scores GEMM: P16 = exp(Q K^T / 32) * 2^-4, row sums fused via atomics =======
__global__ void __launch_bounds__(NT, 2) scores_kernel(
    const __half* __restrict__ Q, const __half* __restrict__ K,
    __half* __restrict__ P, float* __restrict__ rowsum)
{
    extern __shared__ __align__(1024) char smem[];
    const uint32_t sb = smem_u32(smem);
    const long long SD = (long long)Ss * Dd;
    const long long SS2 = (long long)Ss * Ss;
    const int bz = blockIdx.z;
    gemm_body<3>(Q + bz * SD + (long long)blockIdx.y * BM * Dd,
                 K + bz * SD + (long long)blockIdx.x * BN * Dd,
                 nullptr, rowsum + bz * Ss,
                 P + bz * SS2, Ss, Dd, 0.03125f,
                 blockIdx.y * BM, blockIdx.x * BN, sb);
}

// ======= PV GEMM: out = (P16 @ Vt^T) / rowsum[row] =======
__global__ void __launch_bounds__(NT, 2) pv_kernel(
    const __half* __restrict__ P, const __half* __restrict__ Vt,
    const float* __restrict__ rowsum, float* __restrict__ out)
{
    extern __shared__ __align__(1024) char smem[];
    const uint32_t sb = smem_u32(smem);
    const long long SD = (long long)Ss * Dd;
    const long long SS2 = (long long)Ss * Ss;
    const int bz = blockIdx.z;
    gemm_body<4>(P + bz * SS2 + (long long)blockIdx.y * BM * Ss,
                 Vt + bz * SD + (long long)blockIdx.x * BN * Ss,
                 nullptr, const_cast<float*>(rowsum) + bz * Ss,
                 out + bz * SD, Dd, Ss, 1.0f,
                 blockIdx.y * BM, blockIdx.x * BN, sb);
}

// ---------------- merged fp32 -> fp16 convert (x and 3 weights) ----------------
__global__ void cvt_all_kernel(const float* __restrict__ x,
                               const float* __restrict__ wq, const float* __restrict__ wk,
                               const float* __restrict__ wv,
                               __half* __restrict__ x16, __half* __restrict__ W16)
{
    const int b = blockIdx.x;
    const int tid = threadIdx.x;
    const float* src;
    __half* dst;
    int i;
    if (b < 8192) {                 // x: 2097152 float4
        src = x; dst = x16; i = b * 256 + tid;
    } else {                        // weights: 262144 float4 each
        const int wb = b - 8192;
        const int w = wb >> 10;     // 0..2
        src = (w == 0) ? wq : (w == 1) ? wk : wv;
        dst = W16 + (long long)w * Dd * Dd;
        i = (wb & 1023) * 256 + tid;
    }
    const float4 v = reinterpret_cast<const float4*>(src)[i];
    __half2* o = reinterpret_cast<__half2*>(dst);
    o[2 * i]     = __floats2half2_rn(v.x, v.y);
    o[2 * i + 1] = __floats2half2_rn(v.z, v.w);
}

// ---------------- host ----------------
extern "C" void kernel_launch(void* const* d_in, const int* in_sizes, int n_in,
                              void* d_out, int out_size)
{
    const float* x  = (const float*)d_in[0];
    const float* Wq = (const float*)d_in[1];
    const float* bq = (const float*)d_in[2];
    const float* Wk = (const float*)d_in[3];
    const float* bk = (const float*)d_in[4];
    const float* Wv = (const float*)d_in[5];
    const float* bv = (const float*)d_in[6];
    float* out = (float*)d_out;

    __half *x16, *W16, *Q16, *K16, *Vt16, *P16;
    float* rowsum;
    cudaGetSymbolAddress((void**)&x16, g_x16);
    cudaGetSymbolAddress((void**)&W16, g_W16);
    cudaGetSymbolAddress((void**)&Q16, g_Q16);
    cudaGetSymbolAddress((void**)&K16, g_K16);
    cudaGetSymbolAddress((void**)&Vt16, g_Vt16);
    cudaGetSymbolAddress((void**)&P16, g_P16);
    cudaGetSymbolAddress((void**)&rowsum, g_rowsum);

    cudaFuncSetAttribute((const void*)proj_kernel,
                         cudaFuncAttributeMaxDynamicSharedMemorySize, SMEM_BYTES);
    cudaFuncSetAttribute((const void*)scores_kernel,
                         cudaFuncAttributeMaxDynamicSharedMemorySize, SMEM_BYTES);
    cudaFuncSetAttribute((const void*)pv_kernel,
                         cudaFuncAttributeMaxDynamicSharedMemorySize, SMEM_BYTES);

    // 0) zero the fused row-sum accumulator; convert inputs to fp16
    cudaMemsetAsync(rowsum, 0, Bb * Ss * sizeof(float));
    cvt_all_kernel<<<8192 + 3072, 256>>>(x, Wq, Wk, Wv, x16, W16);

    // 1) merged Q/K/Vt projections: one 1536-CTA launch
    proj_kernel<<<1536, NT, SMEM_BYTES>>>(x16, W16, bq, bk, bv, Q16, K16, Vt16);

    // 2) P = exp(Q K^T / 32) * 2^-4 (fp16, unnormalized), row sums accumulated
    const dim3 g2(Ss / BN, Ss / BM, Bb);
    scores_kernel<<<g2, NT, SMEM_BYTES>>>(Q16, K16, P16, rowsum);

    // 3) out = (P @ Vt^T) / rowsum
    const dim3 g3(Dd / BN, Ss / BM, Bb);
    pv_kernel<<<g3, NT, SMEM_BYTES>>>(P16, Vt16, rowsum, out);
}